// round 1
// baseline (speedup 1.0000x reference)
#include <cuda_runtime.h>
#include <cstdint>

// ============================================================================
// LearnableSpectralHamiltonian: y = ifft2(fft2(x) * sqrt_lambda), ortho norm.
// x: (16, 768, 64, 64) f32. Filter sqrt_lambda (64,64) is real & symmetric
// => pack two images as one complex field (exact), one CTA per pair.
// 64-pt FFT = 8x8 four-step per 8-thread group, radix-8 stages in registers.
// ============================================================================

#define HW 64
#define RS 67                 // smem row stride in floats (67%32=3, 8*67%32=24)
#define NPIX 4096
#define NIMG 12288            // 16 * 768
#define NBLK (NIMG / 2)

__device__ float g_filter[NPIX];

__device__ __forceinline__ float2 cadd(float2 a, float2 b) { return make_float2(a.x + b.x, a.y + b.y); }
__device__ __forceinline__ float2 csub(float2 a, float2 b) { return make_float2(a.x - b.x, a.y - b.y); }
__device__ __forceinline__ float2 cmul(float2 a, float2 b) {
    return make_float2(fmaf(a.x, b.x, -a.y * b.y), fmaf(a.x, b.y, a.y * b.x));
}

// multiply by -i (forward) / +i (inverse)
template <bool INV>
__device__ __forceinline__ float2 mul_i(float2 a) {
    return INV ? make_float2(-a.y, a.x) : make_float2(a.y, -a.x);
}

// 8-point DFT, natural order in/out. Forward: W8 = exp(-2*pi*i/8).
template <bool INV>
__device__ __forceinline__ void fft8(float2* a) {
    const float C = 0.70710678118654752440f;
    float2 e0 = a[0], e1 = a[2], e2 = a[4], e3 = a[6];
    float2 o0 = a[1], o1 = a[3], o2 = a[5], o3 = a[7];
    // FFT4 on evens
    float2 t0 = cadd(e0, e2), t1 = csub(e0, e2);
    float2 t2 = cadd(e1, e3), t3 = mul_i<INV>(csub(e1, e3));
    float2 E0 = cadd(t0, t2), E2 = csub(t0, t2);
    float2 E1 = cadd(t1, t3), E3 = csub(t1, t3);
    // FFT4 on odds
    t0 = cadd(o0, o2); t1 = csub(o0, o2);
    t2 = cadd(o1, o3); t3 = mul_i<INV>(csub(o1, o3));
    float2 O0 = cadd(t0, t2), O2 = csub(t0, t2);
    float2 O1 = cadd(t1, t3), O3 = csub(t1, t3);
    // twiddle odd outputs by W8^k
    if (!INV) {
        O1 = make_float2(C * (O1.x + O1.y), C * (O1.y - O1.x));   // W8^1 = C(1-i)
        O2 = make_float2(O2.y, -O2.x);                            // W8^2 = -i
        O3 = make_float2(C * (O3.y - O3.x), C * (-O3.x - O3.y));  // W8^3 = C(-1-i)
    } else {
        O1 = make_float2(C * (O1.x - O1.y), C * (O1.x + O1.y));   // C(1+i)
        O2 = make_float2(-O2.y, O2.x);                            // +i
        O3 = make_float2(C * (-O3.x - O3.y), C * (O3.x - O3.y));  // C(-1+i)
    }
    a[0] = cadd(E0, O0); a[4] = csub(E0, O0);
    a[1] = cadd(E1, O1); a[5] = csub(E1, O1);
    a[2] = cadd(E2, O2); a[6] = csub(E2, O2);
    a[3] = cadd(E3, O3); a[7] = csub(E3, O3);
}

// ============================================================================
// Filter construction (one tiny block).
// g_b = g1 + cumsum(softplus(raw_deltas)); ell = g[bin]; center, clip,
// geometric-mean normalize; f = sqrt(lam) / 4096 (folds ortho norms).
// ============================================================================
__global__ void build_filter_kernel(const float* __restrict__ g1p,
                                    const float* __restrict__ raw_deltas,
                                    const int* __restrict__ bin_idx) {
    __shared__ float gbin[16];
    __shared__ float red[256];
    int tid = threadIdx.x;

    if (tid == 0) {
        float acc = g1p[0];
        gbin[0] = acc;
        #pragma unroll
        for (int i = 0; i < 15; i++) {
            float v = raw_deltas[i];
            float sp = (v > 20.0f) ? v : log1pf(expf(v));
            acc += sp;
            gbin[i + 1] = acc;
        }
    }
    __syncthreads();

    float ell[16];
    float s = 0.0f;
    #pragma unroll
    for (int i = 0; i < 16; i++) {
        int p = tid + 256 * i;
        ell[i] = gbin[bin_idx[p]];
        s += ell[i];
    }
    red[tid] = s;
    __syncthreads();
    for (int off = 128; off > 0; off >>= 1) {
        if (tid < off) red[tid] += red[tid + off];
        __syncthreads();
    }
    float m1 = red[0] * (1.0f / 4096.0f);
    __syncthreads();

    float s2 = 0.0f;
    #pragma unroll
    for (int i = 0; i < 16; i++) {
        float e = ell[i] - m1;
        e = fminf(3.0f, fmaxf(-3.0f, e));
        ell[i] = e;
        s2 += e;
    }
    red[tid] = s2;
    __syncthreads();
    for (int off = 128; off > 0; off >>= 1) {
        if (tid < off) red[tid] += red[tid + off];
        __syncthreads();
    }
    float m2 = red[0] * (1.0f / 4096.0f);

    #pragma unroll
    for (int i = 0; i < 16; i++) {
        int p = tid + 256 * i;
        g_filter[p] = expf(0.5f * (ell[i] - m2)) * (1.0f / 4096.0f);
    }
}

// ============================================================================
// Main kernel: one CTA per image pair. 512 threads = 64 groups x 8 threads.
// Group g handles row g (phases 1,3) and column g (phase 2).
// Four-step 64pt FFT: thread t holds elements {t + 8j}; inner FFT8 over j,
// twiddle W64^{t*k}, 8x8 exchange via smem, outer FFT8 -> X[t + 8k].
// ============================================================================
__global__ void __launch_bounds__(512, 2)
spectral_kernel(const float* __restrict__ x, float* __restrict__ y) {
    __shared__ float Sre[HW * RS];
    __shared__ float Sim[HW * RS];
    __shared__ float2 Wt[64];

    int tid = threadIdx.x;
    if (tid < 64) {
        float sv, cv;
        sincospif(-(float)tid * (1.0f / 32.0f), &sv, &cv);  // exp(-2*pi*i*tid/64)
        Wt[tid] = make_float2(cv, sv);
    }
    int g = tid >> 3;
    int t = tid & 7;
    size_t base = (size_t)blockIdx.x * (2 * NPIX);
    const float* A = x + base;
    const float* B = A + NPIX;
    __syncthreads();

    float2 d[8];
    float* rr = Sre + g * RS;
    float* ri = Sim + g * RS;

    // ---------------- Phase 1: forward FFT along w (row g), global -> smem
    #pragma unroll
    for (int j = 0; j < 8; j++) {
        int idx = (g << 6) + t + (j << 3);
        d[j] = make_float2(A[idx], B[idx]);
    }
    fft8<false>(d);
    #pragma unroll
    for (int k = 1; k < 8; k++) d[k] = cmul(d[k], Wt[t * k]);
    #pragma unroll
    for (int k = 0; k < 8; k++) { rr[(k << 3) + t] = d[k].x; ri[(k << 3) + t] = d[k].y; }
    __syncwarp();
    #pragma unroll
    for (int j = 0; j < 8; j++) { d[j].x = rr[(t << 3) + j]; d[j].y = ri[(t << 3) + j]; }
    fft8<false>(d);
    __syncwarp();
    #pragma unroll
    for (int k = 0; k < 8; k++) { rr[t + (k << 3)] = d[k].x; ri[t + (k << 3)] = d[k].y; }
    __syncthreads();

    // ---------------- Phase 2: column c = g: fwd FFT + filter + inv FFT
    int c = g;
    #pragma unroll
    for (int j = 0; j < 8; j++) {
        int r = t + (j << 3);
        d[j].x = Sre[r * RS + c]; d[j].y = Sim[r * RS + c];
    }
    fft8<false>(d);
    #pragma unroll
    for (int k = 1; k < 8; k++) d[k] = cmul(d[k], Wt[t * k]);
    __syncwarp();
    #pragma unroll
    for (int k = 0; k < 8; k++) {
        int r = (k << 3) + t;
        Sre[r * RS + c] = d[k].x; Sim[r * RS + c] = d[k].y;
    }
    __syncwarp();
    #pragma unroll
    for (int j = 0; j < 8; j++) {
        int r = (t << 3) + j;
        d[j].x = Sre[r * RS + c]; d[j].y = Sim[r * RS + c];
    }
    fft8<false>(d);
    // filter multiply: thread holds X at frequency rows (t + 8k), column c
    #pragma unroll
    for (int k = 0; k < 8; k++) {
        float f = g_filter[((t + (k << 3)) << 6) + c];
        d[k].x *= f; d[k].y *= f;
    }
    // inverse column FFT (input layout identical to fwd output layout)
    fft8<true>(d);
    #pragma unroll
    for (int k = 1; k < 8; k++) {
        float2 w = Wt[t * k];
        d[k] = cmul(d[k], make_float2(w.x, -w.y));
    }
    __syncwarp();
    #pragma unroll
    for (int k = 0; k < 8; k++) {
        int r = (k << 3) + t;
        Sre[r * RS + c] = d[k].x; Sim[r * RS + c] = d[k].y;
    }
    __syncwarp();
    #pragma unroll
    for (int j = 0; j < 8; j++) {
        int r = (t << 3) + j;
        d[j].x = Sre[r * RS + c]; d[j].y = Sim[r * RS + c];
    }
    fft8<true>(d);
    __syncwarp();
    #pragma unroll
    for (int k = 0; k < 8; k++) {
        int r = t + (k << 3);
        Sre[r * RS + c] = d[k].x; Sim[r * RS + c] = d[k].y;
    }
    __syncthreads();

    // ---------------- Phase 3: inverse FFT along w (row g), smem -> global
    #pragma unroll
    for (int j = 0; j < 8; j++) { d[j].x = rr[t + (j << 3)]; d[j].y = ri[t + (j << 3)]; }
    fft8<true>(d);
    #pragma unroll
    for (int k = 1; k < 8; k++) {
        float2 w = Wt[t * k];
        d[k] = cmul(d[k], make_float2(w.x, -w.y));
    }
    __syncwarp();
    #pragma unroll
    for (int k = 0; k < 8; k++) { rr[(k << 3) + t] = d[k].x; ri[(k << 3) + t] = d[k].y; }
    __syncwarp();
    #pragma unroll
    for (int j = 0; j < 8; j++) { d[j].x = rr[(t << 3) + j]; d[j].y = ri[(t << 3) + j]; }
    fft8<true>(d);

    float* Ya = y + base;
    float* Yb = Ya + NPIX;
    #pragma unroll
    for (int k = 0; k < 8; k++) {
        int idx = (g << 6) + t + (k << 3);
        Ya[idx] = d[k].x;
        Yb[idx] = d[k].y;
    }
}

extern "C" void kernel_launch(void* const* d_in, const int* in_sizes, int n_in,
                              void* d_out, int out_size) {
    const float* x   = (const float*)d_in[0];
    const float* g1  = (const float*)d_in[1];
    const float* raw = (const float*)d_in[2];
    const int* bidx  = (const int*)d_in[3];
    float* y = (float*)d_out;

    build_filter_kernel<<<1, 256>>>(g1, raw, bidx);
    spectral_kernel<<<NBLK, 512>>>(x, y);
}

// round 2
// speedup vs baseline: 1.4656x; 1.4656x over previous
#include <cuda_runtime.h>
#include <cstdint>

// ============================================================================
// y = ifft2(fft2(x) * sqrt_lambda), ortho norm. x: (16,768,64,64) f32.
// Real symmetric filter => pack 2 images as one complex field (exact).
// One CTA per pair: 512 thr = 64 groups x 8. 64-pt FFT = radix-8 x radix-8,
// internal 8x8 exchange via shfl_xor butterfly (no smem), inter-dimension
// transposes via padded float2 smem (conflict-free), twiddles in registers.
// ============================================================================

#define NPIX 4096
#define NBLK 6144          // 12288 images / 2
#define RS2  68            // float2 row stride: (68t+c)%16 and (68g+t)%16 both uniform-2
#define RSF  72            // filter float stride: (72c+t)%32 = 8c+t -> all distinct
#define SMEM_BYTES (64*RS2*8 + 64*RSF*4)   // 34816 + 18432 = 53248

__device__ float g_filter[NPIX];   // stored TRANSPOSED: g_filter[c*64 + r]

__device__ __forceinline__ float2 cadd(float2 a, float2 b) { return make_float2(a.x + b.x, a.y + b.y); }
__device__ __forceinline__ float2 csub(float2 a, float2 b) { return make_float2(a.x - b.x, a.y - b.y); }
__device__ __forceinline__ float2 cmul(float2 a, float2 b) {
    return make_float2(fmaf(a.x, b.x, -a.y * b.y), fmaf(a.x, b.y, a.y * b.x));
}
__device__ __forceinline__ float2 cmulc(float2 a, float2 b) {  // a * conj(b)
    return make_float2(fmaf(a.x, b.x, a.y * b.y), fmaf(a.y, b.x, -a.x * b.y));
}

template <bool INV>
__device__ __forceinline__ float2 mul_i(float2 a) {
    return INV ? make_float2(-a.y, a.x) : make_float2(a.y, -a.x);
}

// 8-point DFT, natural order in/out.
template <bool INV>
__device__ __forceinline__ void fft8(float2* a) {
    const float C = 0.70710678118654752440f;
    float2 e0 = a[0], e1 = a[2], e2 = a[4], e3 = a[6];
    float2 o0 = a[1], o1 = a[3], o2 = a[5], o3 = a[7];
    float2 t0 = cadd(e0, e2), t1 = csub(e0, e2);
    float2 t2 = cadd(e1, e3), t3 = mul_i<INV>(csub(e1, e3));
    float2 E0 = cadd(t0, t2), E2 = csub(t0, t2);
    float2 E1 = cadd(t1, t3), E3 = csub(t1, t3);
    t0 = cadd(o0, o2); t1 = csub(o0, o2);
    t2 = cadd(o1, o3); t3 = mul_i<INV>(csub(o1, o3));
    float2 O0 = cadd(t0, t2), O2 = csub(t0, t2);
    float2 O1 = cadd(t1, t3), O3 = csub(t1, t3);
    if (!INV) {
        O1 = make_float2(C * (O1.x + O1.y), C * (O1.y - O1.x));
        O2 = make_float2(O2.y, -O2.x);
        O3 = make_float2(C * (O3.y - O3.x), C * (-O3.x - O3.y));
    } else {
        O1 = make_float2(C * (O1.x - O1.y), C * (O1.x + O1.y));
        O2 = make_float2(-O2.y, O2.x);
        O3 = make_float2(C * (-O3.x - O3.y), C * (O3.x - O3.y));
    }
    a[0] = cadd(E0, O0); a[4] = csub(E0, O0);
    a[1] = cadd(E1, O1); a[5] = csub(E1, O1);
    a[2] = cadd(E2, O2); a[6] = csub(E2, O2);
    a[3] = cadd(E3, O3); a[7] = csub(E3, O3);
}

// 8x8 register transpose across the 8 lanes of a group: (lane, slot)->(slot, lane).
// 3-stage xor butterfly; lane masks {1,2,4} stay inside the aligned 8-lane group.
__device__ __forceinline__ void xpose8(float2* v, int t) {
    #pragma unroll
    for (int b = 0; b < 3; b++) {
        const int m = 1 << b;
        const bool hi = (t & m) != 0;
        #pragma unroll
        for (int s0 = 0; s0 < 8; s0++) {
            if (s0 & m) continue;
            const int s1 = s0 | m;
            float2 send = hi ? v[s0] : v[s1];
            float2 r;
            r.x = __shfl_xor_sync(0xFFFFFFFFu, send.x, m);
            r.y = __shfl_xor_sync(0xFFFFFFFFu, send.y, m);
            if (hi) v[s0] = r; else v[s1] = r;
        }
    }
}

// ============================================================================
// Filter: g_b = g1 + cumsum(softplus); gather, center, clip, geo-mean norm,
// sqrt, fold 1/4096 ortho. Stored transposed: g_filter[c*64 + r].
// ============================================================================
__global__ void build_filter_kernel(const float* __restrict__ g1p,
                                    const float* __restrict__ raw_deltas,
                                    const int* __restrict__ bin_idx) {
    __shared__ float gbin[16];
    __shared__ float red[256];
    int tid = threadIdx.x;

    if (tid == 0) {
        float acc = g1p[0];
        gbin[0] = acc;
        #pragma unroll
        for (int i = 0; i < 15; i++) {
            float v = raw_deltas[i];
            float sp = (v > 20.0f) ? v : log1pf(expf(v));
            acc += sp;
            gbin[i + 1] = acc;
        }
    }
    __syncthreads();

    float ell[16];
    float s = 0.0f;
    #pragma unroll
    for (int i = 0; i < 16; i++) {
        int p = tid + 256 * i;
        ell[i] = gbin[bin_idx[p]];
        s += ell[i];
    }
    red[tid] = s;
    __syncthreads();
    for (int off = 128; off > 0; off >>= 1) {
        if (tid < off) red[tid] += red[tid + off];
        __syncthreads();
    }
    float m1 = red[0] * (1.0f / 4096.0f);
    __syncthreads();

    float s2 = 0.0f;
    #pragma unroll
    for (int i = 0; i < 16; i++) {
        float e = ell[i] - m1;
        e = fminf(3.0f, fmaxf(-3.0f, e));
        ell[i] = e;
        s2 += e;
    }
    red[tid] = s2;
    __syncthreads();
    for (int off = 128; off > 0; off >>= 1) {
        if (tid < off) red[tid] += red[tid + off];
        __syncthreads();
    }
    float m2 = red[0] * (1.0f / 4096.0f);

    #pragma unroll
    for (int i = 0; i < 16; i++) {
        int p = tid + 256 * i;              // p = r*64 + c
        float val = expf(0.5f * (ell[i] - m2)) * (1.0f / 4096.0f);
        g_filter[((p & 63) << 6) | (p >> 6)] = val;   // transposed store
    }
}

// ============================================================================
// Main kernel.
// ============================================================================
__global__ void __launch_bounds__(512, 2)
spectral_kernel(const float* __restrict__ x, float* __restrict__ y) {
    extern __shared__ char smraw[];
    float2* S  = (float2*)smraw;                 // 64 x RS2 float2
    float*  Sf = (float*)(smraw + 64 * RS2 * 8); // 64 x RSF float (transposed filter)

    const int tid = threadIdx.x;
    const int g = tid >> 3;
    const int t = tid & 7;

    // Load transposed filter into smem (fully coalesced both sides).
    #pragma unroll
    for (int i = 0; i < 8; i++) {
        int q = tid + 512 * i;                   // q = c*64 + r
        Sf[(q >> 6) * RSF + (q & 63)] = g_filter[q];
    }

    // Twiddles in registers: w[k-1] = exp(-2*pi*i * t*k / 64), k=1..7.
    float2 w[7];
    #pragma unroll
    for (int k = 1; k < 8; k++) {
        float sv, cv;
        sincospif(-(float)(t * k) * (1.0f / 32.0f), &sv, &cv);
        w[k - 1] = make_float2(cv, sv);
    }

    const size_t base = (size_t)blockIdx.x * (2 * NPIX);
    const float* A = x + base;
    const float* B = A + NPIX;

    float2 d[8];

    // ---------------- Phase A: forward row FFT (row g), global -> smem
    #pragma unroll
    for (int j = 0; j < 8; j++) {
        int idx = (g << 6) + t + (j << 3);
        d[j] = make_float2(A[idx], B[idx]);
    }
    fft8<false>(d);
    #pragma unroll
    for (int k = 1; k < 8; k++) d[k] = cmul(d[k], w[k - 1]);
    xpose8(d, t);
    fft8<false>(d);
    #pragma unroll
    for (int k = 0; k < 8; k++) S[g * RS2 + t + (k << 3)] = d[k];
    __syncthreads();

    // ---------------- Phase B: column c = g: fwd FFT + filter + inv FFT
    const int c = g;
    #pragma unroll
    for (int j = 0; j < 8; j++) d[j] = S[(t + (j << 3)) * RS2 + c];
    fft8<false>(d);
    #pragma unroll
    for (int k = 1; k < 8; k++) d[k] = cmul(d[k], w[k - 1]);
    xpose8(d, t);
    fft8<false>(d);
    // d[k] = X at frequency (row t+8k, col c); filter is real.
    #pragma unroll
    for (int k = 0; k < 8; k++) {
        float f = Sf[c * RSF + t + (k << 3)];
        d[k].x *= f; d[k].y *= f;
    }
    fft8<true>(d);
    #pragma unroll
    for (int k = 1; k < 8; k++) d[k] = cmulc(d[k], w[k - 1]);
    xpose8(d, t);
    fft8<true>(d);
    #pragma unroll
    for (int k = 0; k < 8; k++) S[(t + (k << 3)) * RS2 + c] = d[k];
    __syncthreads();

    // ---------------- Phase C: inverse row FFT (row g), smem -> global
    #pragma unroll
    for (int j = 0; j < 8; j++) d[j] = S[g * RS2 + t + (j << 3)];
    fft8<true>(d);
    #pragma unroll
    for (int k = 1; k < 8; k++) d[k] = cmulc(d[k], w[k - 1]);
    xpose8(d, t);
    fft8<true>(d);

    float* Ya = y + base;
    float* Yb = Ya + NPIX;
    #pragma unroll
    for (int k = 0; k < 8; k++) {
        int idx = (g << 6) + t + (k << 3);
        Ya[idx] = d[k].x;
        Yb[idx] = d[k].y;
    }
}

extern "C" void kernel_launch(void* const* d_in, const int* in_sizes, int n_in,
                              void* d_out, int out_size) {
    const float* x   = (const float*)d_in[0];
    const float* g1  = (const float*)d_in[1];
    const float* raw = (const float*)d_in[2];
    const int* bidx  = (const int*)d_in[3];
    float* y = (float*)d_out;

    static bool attr_set = false;
    if (!attr_set) {
        cudaFuncSetAttribute(spectral_kernel,
                             cudaFuncAttributeMaxDynamicSharedMemorySize, SMEM_BYTES);
        attr_set = true;
    }

    build_filter_kernel<<<1, 256>>>(g1, raw, bidx);
    spectral_kernel<<<NBLK, 512, SMEM_BYTES>>>(x, y);
}

// round 3
// speedup vs baseline: 1.5455x; 1.0546x over previous
#include <cuda_runtime.h>
#include <cstdint>

// ============================================================================
// y = ifft2(fft2(x) * sqrt_lambda), ortho. x: (16,768,64,64) f32.
// Real symmetric filter => pack 2 images as one complex field (exact).
// One CTA (256 thr) per pair; each thread runs TWO independent streams
// (rows g and g+32 / cols c and c+32) for ILP-based latency hiding.
// 64-pt FFT = radix-8 x radix-8; intra-FFT 8x8 exchange via shfl_xor;
// inter-dimension transposes via padded float2 smem (2-way min conflicts).
// ============================================================================

#define NPIX 4096
#define NBLK 6144          // 12288 images / 2
#define RS2  68            // float2 row stride: both access patterns uniform-2-way

__device__ float g_filter[NPIX];   // TRANSPOSED: g_filter[c*64 + r]

__device__ __forceinline__ float2 cadd(float2 a, float2 b) { return make_float2(a.x + b.x, a.y + b.y); }
__device__ __forceinline__ float2 csub(float2 a, float2 b) { return make_float2(a.x - b.x, a.y - b.y); }
__device__ __forceinline__ float2 cmul(float2 a, float2 b) {
    return make_float2(fmaf(a.x, b.x, -a.y * b.y), fmaf(a.x, b.y, a.y * b.x));
}
__device__ __forceinline__ float2 cmulc(float2 a, float2 b) {  // a * conj(b)
    return make_float2(fmaf(a.x, b.x, a.y * b.y), fmaf(a.y, b.x, -a.x * b.y));
}

template <bool INV>
__device__ __forceinline__ float2 mul_i(float2 a) {
    return INV ? make_float2(-a.y, a.x) : make_float2(a.y, -a.x);
}

// 8-point DFT, natural order in/out.
template <bool INV>
__device__ __forceinline__ void fft8(float2* a) {
    const float C = 0.70710678118654752440f;
    float2 e0 = a[0], e1 = a[2], e2 = a[4], e3 = a[6];
    float2 o0 = a[1], o1 = a[3], o2 = a[5], o3 = a[7];
    float2 t0 = cadd(e0, e2), t1 = csub(e0, e2);
    float2 t2 = cadd(e1, e3), t3 = mul_i<INV>(csub(e1, e3));
    float2 E0 = cadd(t0, t2), E2 = csub(t0, t2);
    float2 E1 = cadd(t1, t3), E3 = csub(t1, t3);
    t0 = cadd(o0, o2); t1 = csub(o0, o2);
    t2 = cadd(o1, o3); t3 = mul_i<INV>(csub(o1, o3));
    float2 O0 = cadd(t0, t2), O2 = csub(t0, t2);
    float2 O1 = cadd(t1, t3), O3 = csub(t1, t3);
    if (!INV) {
        O1 = make_float2(C * (O1.x + O1.y), C * (O1.y - O1.x));
        O2 = make_float2(O2.y, -O2.x);
        O3 = make_float2(C * (O3.y - O3.x), C * (-O3.x - O3.y));
    } else {
        O1 = make_float2(C * (O1.x - O1.y), C * (O1.x + O1.y));
        O2 = make_float2(-O2.y, O2.x);
        O3 = make_float2(C * (-O3.x - O3.y), C * (O3.x - O3.y));
    }
    a[0] = cadd(E0, O0); a[4] = csub(E0, O0);
    a[1] = cadd(E1, O1); a[5] = csub(E1, O1);
    a[2] = cadd(E2, O2); a[6] = csub(E2, O2);
    a[3] = cadd(E3, O3); a[7] = csub(E3, O3);
}

// Dual 8x8 register transpose (two independent streams interleaved so the
// 26-cycle shfl latency of one stream hides under the other).
__device__ __forceinline__ void xpose8x2(float2* v, float2* u, int t) {
    #pragma unroll
    for (int b = 0; b < 3; b++) {
        const int m = 1 << b;
        const bool hi = (t & m) != 0;
        #pragma unroll
        for (int s0 = 0; s0 < 8; s0++) {
            if (s0 & m) continue;
            const int s1 = s0 | m;
            float2 sv = hi ? v[s0] : v[s1];
            float2 su = hi ? u[s0] : u[s1];
            float2 rv, ru;
            rv.x = __shfl_xor_sync(0xFFFFFFFFu, sv.x, m);
            rv.y = __shfl_xor_sync(0xFFFFFFFFu, sv.y, m);
            ru.x = __shfl_xor_sync(0xFFFFFFFFu, su.x, m);
            ru.y = __shfl_xor_sync(0xFFFFFFFFu, su.y, m);
            if (hi) { v[s0] = rv; u[s0] = ru; } else { v[s1] = rv; u[s1] = ru; }
        }
    }
}

// ============================================================================
// Filter build (tiny). Stored transposed: g_filter[c*64 + r].
// ============================================================================
__global__ void build_filter_kernel(const float* __restrict__ g1p,
                                    const float* __restrict__ raw_deltas,
                                    const int* __restrict__ bin_idx) {
    __shared__ float gbin[16];
    __shared__ float red[256];
    int tid = threadIdx.x;

    if (tid == 0) {
        float acc = g1p[0];
        gbin[0] = acc;
        #pragma unroll
        for (int i = 0; i < 15; i++) {
            float v = raw_deltas[i];
            float sp = (v > 20.0f) ? v : log1pf(expf(v));
            acc += sp;
            gbin[i + 1] = acc;
        }
    }
    __syncthreads();

    float ell[16];
    float s = 0.0f;
    #pragma unroll
    for (int i = 0; i < 16; i++) {
        int p = tid + 256 * i;
        ell[i] = gbin[bin_idx[p]];
        s += ell[i];
    }
    red[tid] = s;
    __syncthreads();
    for (int off = 128; off > 0; off >>= 1) {
        if (tid < off) red[tid] += red[tid + off];
        __syncthreads();
    }
    float m1 = red[0] * (1.0f / 4096.0f);
    __syncthreads();

    float s2 = 0.0f;
    #pragma unroll
    for (int i = 0; i < 16; i++) {
        float e = ell[i] - m1;
        e = fminf(3.0f, fmaxf(-3.0f, e));
        ell[i] = e;
        s2 += e;
    }
    red[tid] = s2;
    __syncthreads();
    for (int off = 128; off > 0; off >>= 1) {
        if (tid < off) red[tid] += red[tid + off];
        __syncthreads();
    }
    float m2 = red[0] * (1.0f / 4096.0f);

    #pragma unroll
    for (int i = 0; i < 16; i++) {
        int p = tid + 256 * i;              // p = r*64 + c
        float val = expf(0.5f * (ell[i] - m2)) * (1.0f / 4096.0f);
        g_filter[((p & 63) << 6) | (p >> 6)] = val;   // transposed
    }
}

// ============================================================================
// Main kernel: 256 threads, one image pair, dual streams per thread.
// ============================================================================
__global__ void __launch_bounds__(256, 3)
spectral_kernel(const float* __restrict__ x, float* __restrict__ y) {
    __shared__ float2 S[64 * RS2];   // 34816 B (static)

    const int tid = threadIdx.x;
    const int g = tid >> 3;          // 0..31
    const int t = tid & 7;

    // Twiddles: w[k-1] = exp(-2*pi*i * t*k / 64), k=1..7.
    float2 w[7];
    #pragma unroll
    for (int k = 1; k < 8; k++) {
        float sv, cv;
        sincospif(-(float)(t * k) * (1.0f / 32.0f), &sv, &cv);
        w[k - 1] = make_float2(cv, sv);
    }

    const size_t base = (size_t)blockIdx.x * (2 * NPIX);
    const float* A = x + base;
    const float* B = A + NPIX;

    float2 d[8], e[8];
    const int g2 = g + 32;

    // ---------------- Phase A: forward row FFT, rows g and g+32
    #pragma unroll
    for (int j = 0; j < 8; j++) {
        int i1 = (g << 6) + t + (j << 3);
        int i2 = (g2 << 6) + t + (j << 3);
        d[j] = make_float2(A[i1], B[i1]);
        e[j] = make_float2(A[i2], B[i2]);
    }
    fft8<false>(d); fft8<false>(e);
    #pragma unroll
    for (int k = 1; k < 8; k++) { d[k] = cmul(d[k], w[k - 1]); e[k] = cmul(e[k], w[k - 1]); }
    xpose8x2(d, e, t);
    fft8<false>(d); fft8<false>(e);
    #pragma unroll
    for (int k = 0; k < 8; k++) {
        S[g  * RS2 + t + (k << 3)] = d[k];
        S[g2 * RS2 + t + (k << 3)] = e[k];
    }
    __syncthreads();

    // ---------------- Phase B: columns c=g and c=g+32
    const int c1 = g, c2 = g2;
    #pragma unroll
    for (int j = 0; j < 8; j++) {
        int r = t + (j << 3);
        d[j] = S[r * RS2 + c1];
        e[j] = S[r * RS2 + c2];
    }
    fft8<false>(d); fft8<false>(e);
    #pragma unroll
    for (int k = 1; k < 8; k++) { d[k] = cmul(d[k], w[k - 1]); e[k] = cmul(e[k], w[k - 1]); }
    xpose8x2(d, e, t);
    fft8<false>(d); fft8<false>(e);
    // filter at (row t+8k, col c); transposed table, L1-resident
    #pragma unroll
    for (int k = 0; k < 8; k++) {
        int r = t + (k << 3);
        float f1 = __ldg(&g_filter[(c1 << 6) + r]);
        float f2 = __ldg(&g_filter[(c2 << 6) + r]);
        d[k].x *= f1; d[k].y *= f1;
        e[k].x *= f2; e[k].y *= f2;
    }
    fft8<true>(d); fft8<true>(e);
    #pragma unroll
    for (int k = 1; k < 8; k++) { d[k] = cmulc(d[k], w[k - 1]); e[k] = cmulc(e[k], w[k - 1]); }
    xpose8x2(d, e, t);
    fft8<true>(d); fft8<true>(e);
    __syncthreads();   // ensure phase-B reads done before overwrite
    #pragma unroll
    for (int k = 0; k < 8; k++) {
        int r = t + (k << 3);
        S[r * RS2 + c1] = d[k];
        S[r * RS2 + c2] = e[k];
    }
    __syncthreads();

    // ---------------- Phase C: inverse row FFT, rows g and g+32 -> gmem
    #pragma unroll
    for (int j = 0; j < 8; j++) {
        d[j] = S[g  * RS2 + t + (j << 3)];
        e[j] = S[g2 * RS2 + t + (j << 3)];
    }
    fft8<true>(d); fft8<true>(e);
    #pragma unroll
    for (int k = 1; k < 8; k++) { d[k] = cmulc(d[k], w[k - 1]); e[k] = cmulc(e[k], w[k - 1]); }
    xpose8x2(d, e, t);
    fft8<true>(d); fft8<true>(e);

    float* Ya = y + base;
    float* Yb = Ya + NPIX;
    #pragma unroll
    for (int k = 0; k < 8; k++) {
        int i1 = (g << 6) + t + (k << 3);
        int i2 = (g2 << 6) + t + (k << 3);
        Ya[i1] = d[k].x;
        Yb[i1] = d[k].y;
        Ya[i2] = e[k].x;
        Yb[i2] = e[k].y;
    }
}

extern "C" void kernel_launch(void* const* d_in, const int* in_sizes, int n_in,
                              void* d_out, int out_size) {
    const float* x   = (const float*)d_in[0];
    const float* g1  = (const float*)d_in[1];
    const float* raw = (const float*)d_in[2];
    const int* bidx  = (const int*)d_in[3];
    float* y = (float*)d_out;

    build_filter_kernel<<<1, 256>>>(g1, raw, bidx);
    spectral_kernel<<<NBLK, 256>>>(x, y);
}

// round 4
// speedup vs baseline: 1.6528x; 1.0694x over previous
#include <cuda_runtime.h>
#include <cstdint>

// ============================================================================
// y = ifft2(fft2(x) * sqrt_lambda), ortho. x: (16,768,64,64) f32.
// Pack 2 images as one complex field (filter real & symmetric => exact).
// One CTA (64 thr) per pair; EACH THREAD owns a full 64-pt line in registers.
// 64-pt FFT = in-register 8x8 four-step (transpose = register renaming, free).
// Only 2 smem transposes total (col<->row); no shuffles anywhere.
// ============================================================================

#define NPIX 4096
#define NBLK 6144           // 12288 images / 2
#define RSF 68              // plane stride in floats (17 float4)

__device__ float  g_perm[NPIX];   // filter, permuted: g_perm[r*64 + q] = f[r][swap(q)]
__device__ float2 g_tw[64];       // W64^{b*c} at [b*8+c]

__device__ __forceinline__ float2 cadd(float2 a, float2 b) { return make_float2(a.x + b.x, a.y + b.y); }
__device__ __forceinline__ float2 csub(float2 a, float2 b) { return make_float2(a.x - b.x, a.y - b.y); }
__device__ __forceinline__ float2 cmul(float2 a, float2 b) {
    return make_float2(fmaf(a.x, b.x, -a.y * b.y), fmaf(a.x, b.y, a.y * b.x));
}
__device__ __forceinline__ float2 cmulc(float2 a, float2 b) {  // a * conj(b)
    return make_float2(fmaf(a.x, b.x, a.y * b.y), fmaf(a.y, b.x, -a.x * b.y));
}

template <bool INV>
__device__ __forceinline__ float2 mul_i(float2 a) {
    return INV ? make_float2(-a.y, a.x) : make_float2(a.y, -a.x);
}

// 8-point DFT, natural order in/out, in place.
template <bool INV>
__device__ __forceinline__ void fft8(float2* a) {
    const float C = 0.70710678118654752440f;
    float2 e0 = a[0], e1 = a[2], e2 = a[4], e3 = a[6];
    float2 o0 = a[1], o1 = a[3], o2 = a[5], o3 = a[7];
    float2 t0 = cadd(e0, e2), t1 = csub(e0, e2);
    float2 t2 = cadd(e1, e3), t3 = mul_i<INV>(csub(e1, e3));
    float2 E0 = cadd(t0, t2), E2 = csub(t0, t2);
    float2 E1 = cadd(t1, t3), E3 = csub(t1, t3);
    t0 = cadd(o0, o2); t1 = csub(o0, o2);
    t2 = cadd(o1, o3); t3 = mul_i<INV>(csub(o1, o3));
    float2 O0 = cadd(t0, t2), O2 = csub(t0, t2);
    float2 O1 = cadd(t1, t3), O3 = csub(t1, t3);
    if (!INV) {
        O1 = make_float2(C * (O1.x + O1.y), C * (O1.y - O1.x));
        O2 = make_float2(O2.y, -O2.x);
        O3 = make_float2(C * (O3.y - O3.x), C * (-O3.x - O3.y));
    } else {
        O1 = make_float2(C * (O1.x - O1.y), C * (O1.x + O1.y));
        O2 = make_float2(-O2.y, O2.x);
        O3 = make_float2(C * (-O3.x - O3.y), C * (O3.x - O3.y));
    }
    a[0] = cadd(E0, O0); a[4] = csub(E0, O0);
    a[1] = cadd(E1, O1); a[5] = csub(E1, O1);
    a[2] = cadd(E2, O2); a[6] = csub(E2, O2);
    a[3] = cadd(E3, O3); a[7] = csub(E3, O3);
}

// 64-pt FFT, natural-order input. Output digit-swapped: freq (c+8d) at slot (8c+d).
template <bool INV>
__device__ __forceinline__ void fft64_nat(float2* v, const float2* Tw) {
    #pragma unroll
    for (int b = 0; b < 8; b++) {
        float2 a[8];
        #pragma unroll
        for (int j = 0; j < 8; j++) a[j] = v[b + 8 * j];
        fft8<INV>(a);
        #pragma unroll
        for (int j = 0; j < 8; j++) v[b + 8 * j] = a[j];
    }
    #pragma unroll
    for (int b = 1; b < 8; b++)
        #pragma unroll
        for (int c = 1; c < 8; c++) {
            float2 t = Tw[b * 8 + c];
            v[8 * c + b] = INV ? cmulc(v[8 * c + b], t) : cmul(v[8 * c + b], t);
        }
    #pragma unroll
    for (int c = 0; c < 8; c++) fft8<INV>(v + 8 * c);
}

// 64-pt FFT, digit-swapped input (index c+8d at slot 8c+d), natural-order output.
template <bool INV>
__device__ __forceinline__ void fft64_swapin(float2* v, const float2* Tw) {
    #pragma unroll
    for (int c = 0; c < 8; c++) fft8<INV>(v + 8 * c);
    #pragma unroll
    for (int c = 1; c < 8; c++)
        #pragma unroll
        for (int e = 1; e < 8; e++) {
            float2 t = Tw[c * 8 + e];
            v[8 * c + e] = INV ? cmulc(v[8 * c + e], t) : cmul(v[8 * c + e], t);
        }
    #pragma unroll
    for (int e = 0; e < 8; e++) {
        float2 a[8];
        #pragma unroll
        for (int cc = 0; cc < 8; cc++) a[cc] = v[8 * cc + e];
        fft8<INV>(a);
        #pragma unroll
        for (int f = 0; f < 8; f++) v[e + 8 * f] = a[f];
    }
}

// ============================================================================
// Filter + twiddle-table build (tiny, one block).
// ============================================================================
__global__ void build_filter_kernel(const float* __restrict__ g1p,
                                    const float* __restrict__ raw_deltas,
                                    const int* __restrict__ bin_idx) {
    __shared__ float gbin[16];
    __shared__ float red[256];
    int tid = threadIdx.x;

    if (tid < 64) {  // twiddle table W64^{b*c}
        int b = tid >> 3, c = tid & 7;
        float sv, cv;
        sincospif(-(float)(b * c) * (1.0f / 32.0f), &sv, &cv);
        g_tw[tid] = make_float2(cv, sv);
    }

    if (tid == 0) {
        float acc = g1p[0];
        gbin[0] = acc;
        #pragma unroll
        for (int i = 0; i < 15; i++) {
            float v = raw_deltas[i];
            float sp = (v > 20.0f) ? v : log1pf(expf(v));
            acc += sp;
            gbin[i + 1] = acc;
        }
    }
    __syncthreads();

    float ell[16];
    float s = 0.0f;
    #pragma unroll
    for (int i = 0; i < 16; i++) {
        int p = tid + 256 * i;
        ell[i] = gbin[bin_idx[p]];
        s += ell[i];
    }
    red[tid] = s;
    __syncthreads();
    for (int off = 128; off > 0; off >>= 1) {
        if (tid < off) red[tid] += red[tid + off];
        __syncthreads();
    }
    float m1 = red[0] * (1.0f / 4096.0f);
    __syncthreads();

    float s2 = 0.0f;
    #pragma unroll
    for (int i = 0; i < 16; i++) {
        float e = ell[i] - m1;
        e = fminf(3.0f, fmaxf(-3.0f, e));
        ell[i] = e;
        s2 += e;
    }
    red[tid] = s2;
    __syncthreads();
    for (int off = 128; off > 0; off >>= 1) {
        if (tid < off) red[tid] += red[tid + off];
        __syncthreads();
    }
    float m2 = red[0] * (1.0f / 4096.0f);

    #pragma unroll
    for (int i = 0; i < 16; i++) {
        int p = tid + 256 * i;              // p = r*64 + j
        float val = expf(0.5f * (ell[i] - m2)) * (1.0f / 4096.0f);
        int j = p & 63;
        int q = ((j & 7) << 3) | (j >> 3);  // swap(j): slot that holds column j
        g_perm[(p & ~63) | q] = val;
    }
}

// ============================================================================
// Main kernel: 64 threads per pair. Thread c owns column c.
// ============================================================================
__global__ void __launch_bounds__(64, 5)
spectral_kernel(const float* __restrict__ x, float* __restrict__ y) {
    __shared__ float4 P0[64 * 17];   // re plane: 64 rows x 68 floats
    __shared__ float4 P1[64 * 17];   // im plane
    __shared__ float2 Tw[64];

    float* Sre = (float*)P0;
    float* Sim = (float*)P1;

    const int c = threadIdx.x;
    const size_t base = (size_t)blockIdx.x * (2 * NPIX);
    const float* A = x + base;
    const float* B = A + NPIX;

    float2 v[64];

    // Load column c of both images (coalesced; 128 independent LDGs).
    #pragma unroll
    for (int i = 0; i < 64; i++) {
        v[i].x = A[i * 64 + c];
        v[i].y = B[i * 64 + c];
    }
    Tw[c] = g_tw[c];
    __syncthreads();

    // Forward column FFT in registers.
    fft64_nat<false>(v, Tw);

    // Transpose 1: un-swap to natural freq-row order while storing.
    #pragma unroll
    for (int m = 0; m < 64; m++) {
        int s = ((m & 7) << 3) | (m >> 3);        // slot holding freq m
        Sre[m * RSF + c] = v[s].x;
        Sim[m * RSF + c] = v[s].y;
    }
    __syncthreads();

    // Row phase: thread r = c owns freq-row r (natural column order), float4 loads.
    const int r = c;
    #pragma unroll
    for (int k = 0; k < 16; k++) {
        float4 re = P0[r * 17 + k];
        float4 im = P1[r * 17 + k];
        v[4 * k + 0] = make_float2(re.x, im.x);
        v[4 * k + 1] = make_float2(re.y, im.y);
        v[4 * k + 2] = make_float2(re.z, im.z);
        v[4 * k + 3] = make_float2(re.w, im.w);
    }

    fft64_nat<false>(v, Tw);    // swapped output: slot q holds col-freq swap(q)

    // Filter (table pre-permuted to slot order).
    const float4* F = (const float4*)g_perm;
    #pragma unroll
    for (int k = 0; k < 16; k++) {
        float4 f = F[r * 16 + k];
        v[4 * k + 0].x *= f.x; v[4 * k + 0].y *= f.x;
        v[4 * k + 1].x *= f.y; v[4 * k + 1].y *= f.y;
        v[4 * k + 2].x *= f.z; v[4 * k + 2].y *= f.z;
        v[4 * k + 3].x *= f.w; v[4 * k + 3].y *= f.w;
    }

    fft64_swapin<true>(v, Tw);  // natural spatial-col output

    // Transpose 2: store rows (float4), read columns (scalar).
    #pragma unroll
    for (int k = 0; k < 16; k++) {
        P0[r * 17 + k] = make_float4(v[4 * k].x, v[4 * k + 1].x, v[4 * k + 2].x, v[4 * k + 3].x);
        P1[r * 17 + k] = make_float4(v[4 * k].y, v[4 * k + 1].y, v[4 * k + 2].y, v[4 * k + 3].y);
    }
    __syncthreads();

    #pragma unroll
    for (int i = 0; i < 64; i++) {
        v[i].x = Sre[i * RSF + c];
        v[i].y = Sim[i * RSF + c];
    }

    // Inverse column FFT (natural freq-row in, swapped spatial out).
    fft64_nat<true>(v, Tw);

    float* Ya = y + base;
    float* Yb = Ya + NPIX;
    #pragma unroll
    for (int i = 0; i < 64; i++) {
        int s = ((i & 7) << 3) | (i >> 3);        // slot holding spatial row i
        Ya[i * 64 + c] = v[s].x;
        Yb[i * 64 + c] = v[s].y;
    }
}

extern "C" void kernel_launch(void* const* d_in, const int* in_sizes, int n_in,
                              void* d_out, int out_size) {
    const float* x   = (const float*)d_in[0];
    const float* g1  = (const float*)d_in[1];
    const float* raw = (const float*)d_in[2];
    const int* bidx  = (const int*)d_in[3];
    float* y = (float*)d_out;

    build_filter_kernel<<<1, 256>>>(g1, raw, bidx);
    spectral_kernel<<<NBLK, 64>>>(x, y);
}